// round 2
// baseline (speedup 1.0000x reference)
#include <cuda_runtime.h>

// SchurDecompositionLinear: W = P(T) @ P(I)^T where P(M) = M * H0*H1*...*H255
// (Householder reflectors). Since Q = H0...H255 is orthogonal, W = T*Q*Q^T = T.
// T is block-diagonal with 2x2 blocks gamma_k * [[cos, -sin],[sin, cos]].
// So out = x @ T is a per-column-pair rotation:
//   out[:,2k]   =  x[:,2k]*(g*c) + x[:,2k+1]*(g*s)
//   out[:,2k+1] = -x[:,2k]*(g*s) + x[:,2k+1]*(g*c)
// Pure streaming kernel: 64MB in + 64MB out @ ~8TB/s.

#define N_COLS 256
#define N_PAIRS 128
#define F4_PER_ROW 64   // 256 floats / 4

__global__ void schur_rot_kernel(const float4* __restrict__ x,
                                 const float* __restrict__ theta,
                                 const float* __restrict__ gamma,
                                 float4* __restrict__ out,
                                 int n4) {
    __shared__ float2 sc[N_PAIRS];  // (g*cos, g*sin) per pair
    int tid = threadIdx.x;
    if (tid < N_PAIRS) {
        float s, c;
        sincosf(theta[tid], &s, &c);
        float g = gamma[tid];
        sc[tid] = make_float2(g * c, g * s);
    }
    __syncthreads();

    int idx = blockIdx.x * blockDim.x + tid;
    if (idx >= n4) return;

    int col4 = idx & (F4_PER_ROW - 1);  // float4 index within the row
    int pair = col4 << 1;               // first pair index covered by this float4

    float4 v = x[idx];
    float2 p0 = sc[pair];
    float2 p1 = sc[pair + 1];

    float4 r;
    r.x =  v.x * p0.x + v.y * p0.y;
    r.y = -v.x * p0.y + v.y * p0.x;
    r.z =  v.z * p1.x + v.w * p1.y;
    r.w = -v.z * p1.y + v.w * p1.x;

    out[idx] = r;
}

extern "C" void kernel_launch(void* const* d_in, const int* in_sizes, int n_in,
                              void* d_out, int out_size) {
    // inputs: x [65536,256] f32, U [256,256] f32 (unused), theta [128], gamma [128]
    const float4* x     = (const float4*)d_in[0];
    const float*  theta = (const float*)d_in[2];
    const float*  gamma = (const float*)d_in[3];
    float4* out = (float4*)d_out;

    int n4 = out_size / 4;                 // 65536*256/4 = 4194304
    int threads = 256;
    int blocks = (n4 + threads - 1) / threads;
    schur_rot_kernel<<<blocks, threads>>>(x, theta, gamma, out, n4);
}

// round 3
// speedup vs baseline: 1.1731x; 1.1731x over previous
#include <cuda_runtime.h>

// SchurDecompositionLinear: W = P(T)@P(I)^T = T*Q*Q^T = T (Q orthogonal).
// out = x @ T is a per-column-pair 2x2 rotation. Pure HBM stream: 67MB in,
// 67MB out. Persistent grid-stride kernel; column (hence rotation coeffs)
// is loop-invariant per thread -> coefficients computed once, no smem/barrier.
// Streaming ld/st hints (.cs) since data has zero reuse.

#define F4_PER_ROW 64            // 256 floats / 4
#define N4_TOTAL   4194304       // 65536 * 256 / 4
#define BLOCKS     1024
#define THREADS    256
#define TRIPS      16            // N4_TOTAL / (BLOCKS*THREADS)
#define UNROLL     4

__global__ void __launch_bounds__(THREADS, 8)
schur_rot_kernel(const float4* __restrict__ x,
                 const float* __restrict__ theta,
                 const float* __restrict__ gamma,
                 float4* __restrict__ out,
                 int n4) {
    const int tid  = threadIdx.x;
    const int col4 = tid & (F4_PER_ROW - 1);   // loop-invariant: stride % 64 == 0
    const int pair = col4 << 1;

    float s0, c0, s1, c1;
    sincosf(theta[pair],     &s0, &c0);
    sincosf(theta[pair + 1], &s1, &c1);
    const float g0 = gamma[pair], g1 = gamma[pair + 1];
    const float a0 = g0 * c0, b0 = g0 * s0;    // (gc, gs) pair 0
    const float a1 = g1 * c1, b1 = g1 * s1;    // (gc, gs) pair 1

    const int stride = gridDim.x * blockDim.x; // multiple of 64
    int idx = blockIdx.x * blockDim.x + tid;

    if (n4 == N4_TOTAL && gridDim.x == BLOCKS) {
        // exact: TRIPS iterations, unrolled with batched loads for MLP
        #pragma unroll
        for (int t = 0; t < TRIPS / UNROLL; ++t) {
            float4 v[UNROLL];
            #pragma unroll
            for (int u = 0; u < UNROLL; ++u)
                v[u] = __ldcs(&x[idx + u * stride]);
            #pragma unroll
            for (int u = 0; u < UNROLL; ++u) {
                float4 r;
                r.x =  v[u].x * a0 + v[u].y * b0;
                r.y = -v[u].x * b0 + v[u].y * a0;
                r.z =  v[u].z * a1 + v[u].w * b1;
                r.w = -v[u].z * b1 + v[u].w * a1;
                __stcs(&out[idx + u * stride], r);
            }
            idx += UNROLL * stride;
        }
    } else {
        for (; idx < n4; idx += stride) {
            float4 v = __ldcs(&x[idx]);
            float4 r;
            r.x =  v.x * a0 + v.y * b0;
            r.y = -v.x * b0 + v.y * a0;
            r.z =  v.z * a1 + v.w * b1;
            r.w = -v.z * b1 + v.w * a1;
            __stcs(&out[idx], r);
        }
    }
}

extern "C" void kernel_launch(void* const* d_in, const int* in_sizes, int n_in,
                              void* d_out, int out_size) {
    const float4* x     = (const float4*)d_in[0];
    const float*  theta = (const float*)d_in[2];
    const float*  gamma = (const float*)d_in[3];
    float4* out = (float4*)d_out;

    int n4 = out_size / 4;
    schur_rot_kernel<<<BLOCKS, THREADS>>>(x, theta, gamma, out, n4);
}